// round 12
// baseline (speedup 1.0000x reference)
#include <cuda_runtime.h>
#include <math.h>

#define Nn   50000
#define Ee   500000
#define SDv  128
#define HIDv 64
#define K1v  257
#define M3v  134
#define M3P  136
#define TILE 64
#define TEP  65
#define TRS  68
#define NT   256
#define NTILES_E ((Ee + TILE - 1) / TILE)
#define NTILES_N ((Nn + TILE - 1) / TILE)

// ---- edge-kernel shared memory ----
#define OW2 0
#define OB2 (OW2 + HIDv*HIDv)
#define OW3 (OB2 + HIDv)
#define OB3 (OW3 + HIDv*M3P)
#define OWD (OB3 + M3P)
#define OB1 (OWD + HIDv)
#define OH1 (OB1 + HIDv)
#define OMD (OH1 + TILE*TRS)
#define OMS (OMD + TILE)
#define OMC (OMS + TILE)
#define ODD (OMC + TILE)
#define OGV (ODD + TILE)
#define SME_FLOATS (OGV + 6*TILE)
#define SME_BYTES (SME_FLOATS * 4)     // ~72.5 KB -> 3 CTAs/SM

// ---- PQ kernel smem (column-split halves) ----
#define OWh 0
#define OXh (OWh + 128*64)
#define SMP_FLOATS (OXh + SDv*TEP)
#define SMP_BYTES (SMP_FLOATS * 4)     // ~66 KB -> 3 CTAs/SM

// ---- node kernel smem (all weights in smem, 1 CTA/SM) ----
#define OWn1 0
#define OBn1 (OWn1 + 2*SDv*HIDv)
#define OWn2 (OBn1 + HIDv)
#define OBn2 (OWn2 + HIDv*SDv)
#define OX   (OBn2 + SDv)
#define OU   (OX + 2*SDv*TEP)
#define SMN_FLOATS (OU + HIDv*TEP)
#define SMN_BYTES (SMN_FLOATS * 4)

__device__ float g_s[(size_t)Nn * SDv];
__device__ float g_v[(size_t)Nn * 9];
__device__ float g_sagg[(size_t)Nn * SDv];
__device__ float g_vagg[(size_t)Nn * 9];
__device__ float g_pq[(size_t)Nn * 128];
__device__ float g_cnt[Nn];
__device__ float g_inv[Nn];

typedef unsigned long long u64;

__device__ __forceinline__ float silu_f(float x) { return x / (1.0f + __expf(-x)); }

__device__ __forceinline__ void red4(float* p, float a, float b, float c, float d) {
    asm volatile("red.global.add.v4.f32 [%0], {%1,%2,%3,%4};"
                 :: "l"(p), "f"(a), "f"(b), "f"(c), "f"(d) : "memory");
}
__device__ __forceinline__ u64 splat2(float a) {
    u64 r; asm("mov.b64 %0, {%1, %1};" : "=l"(r) : "f"(a)); return r;
}
__device__ __forceinline__ void ffma2(u64& acc, u64 a2, u64 w2) {
    asm("fma.rn.f32x2 %0, %1, %2, %0;" : "+l"(acc) : "l"(a2), "l"(w2));
}
__device__ __forceinline__ void unpack2(u64 p, float& lo, float& hi) {
    asm("mov.b64 {%0, %1}, %2;" : "=f"(lo), "=f"(hi) : "l"(p));
}

// -------------------- init / misc --------------------
__global__ void k_init(const float* __restrict__ s, const float* __restrict__ v) {
    int i = blockIdx.x * blockDim.x + threadIdx.x;
    if (i < Nn * SDv) g_s[i] = s[i];
    if (i < Nn * 9)   g_v[i] = v[i];
    if (i < Nn)       g_cnt[i] = 0.0f;
}
__global__ void k_count(const int* __restrict__ dst) {
    int e = blockIdx.x * blockDim.x + threadIdx.x;
    if (e < Ee) atomicAdd(&g_cnt[dst[e]], 1.0f);
}
__global__ void k_inv() {
    int i = blockIdx.x * blockDim.x + threadIdx.x;
    if (i < Nn) g_inv[i] = 1.0f / fmaxf(g_cnt[i], 1.0f);
}

// -------------------- PQ precompute (column-split, 3 CTAs/SM, + zero agg) --------------------
__global__ void __launch_bounds__(NT, 3)
k_pq(const float* __restrict__ W1g, int l)
{
    extern __shared__ float sm[];
    const int tid = threadIdx.x;
    const int w = tid >> 5, lane = tid & 31;
    const float* W1 = W1g + (size_t)l * K1v * HIDv;
    const int half = blockIdx.x & 1;
    const float* Wh = W1 + half * 128 * 64;

    for (int i = blockIdx.x * NT + tid; i < Nn * SDv; i += gridDim.x * NT) g_sagg[i] = 0.0f;
    for (int i = blockIdx.x * NT + tid; i < Nn * 9; i += gridDim.x * NT) g_vagg[i] = 0.0f;

    for (int i = tid; i < 128 * 64; i += NT) sm[OWh + i] = Wh[i];
    __syncthreads();

    const int tstep = gridDim.x >> 1;
    for (int tile = (blockIdx.x >> 1); tile < NTILES_N; tile += tstep) {
        const int n0 = tile * TILE;
        const int nn = min(TILE, Nn - n0);

        #pragma unroll 4
        for (int i = tid; i < TILE * SDv; i += NT) {
            int n = i >> 7, k = i & 127;
            sm[OXh + k * TEP + n] = (n < nn) ? g_s[(size_t)(n0 + n) * SDv + k] : 0.0f;
        }
        __syncthreads();

        {
            u64 p0[4], p1[4];
            #pragma unroll
            for (int j = 0; j < 4; ++j) { p0[j] = 0ull; p1[j] = 0ull; }
            const int cb = 8 * w;
            #pragma unroll 4
            for (int k = 0; k < 128; ++k) {
                u64 A0 = splat2(sm[OXh + k * TEP + lane]);
                u64 A1 = splat2(sm[OXh + k * TEP + lane + 32]);
                const ulonglong2* wr = (const ulonglong2*)&sm[OWh + k * 64 + cb];
                ulonglong2 w0 = wr[0], w1 = wr[1];
                ffma2(p0[0], A0, w0.x); ffma2(p0[1], A0, w0.y);
                ffma2(p0[2], A0, w1.x); ffma2(p0[3], A0, w1.y);
                ffma2(p1[0], A1, w0.x); ffma2(p1[1], A1, w0.y);
                ffma2(p1[2], A1, w1.x); ffma2(p1[3], A1, w1.y);
            }
            if (lane < nn) {
                float4* op = (float4*)&g_pq[(size_t)(n0 + lane) * 128 + half * 64 + cb];
                float o0, o1, o2, o3, o4, o5, o6, o7;
                unpack2(p0[0], o0, o1); unpack2(p0[1], o2, o3);
                unpack2(p0[2], o4, o5); unpack2(p0[3], o6, o7);
                op[0] = make_float4(o0, o1, o2, o3);
                op[1] = make_float4(o4, o5, o6, o7);
            }
            if (lane + 32 < nn) {
                float4* op = (float4*)&g_pq[(size_t)(n0 + lane + 32) * 128 + half * 64 + cb];
                float o0, o1, o2, o3, o4, o5, o6, o7;
                unpack2(p1[0], o0, o1); unpack2(p1[1], o2, o3);
                unpack2(p1[2], o4, o5); unpack2(p1[3], o6, o7);
                op[0] = make_float4(o0, o1, o2, o3);
                op[1] = make_float4(o4, o5, o6, o7);
            }
        }
        __syncthreads();
    }
}

// -------------------- fused edge kernel (3 CTAs/SM) --------------------
__global__ void __launch_bounds__(NT, 3)
k_edge(const int* __restrict__ dst, const int* __restrict__ src,
       const float* __restrict__ dv, const float* __restrict__ rv,
       const float* __restrict__ W1g, const float* __restrict__ b1g,
       const float* __restrict__ W2g, const float* __restrict__ b2g,
       const float* __restrict__ W3g, const float* __restrict__ b3g,
       int l)
{
    extern __shared__ float sm[];
    const int tid = threadIdx.x;
    const int w = tid >> 5, lane = tid & 31;

    const float* W1 = W1g + (size_t)l * K1v * HIDv;
    const float* b1 = b1g + l * HIDv;
    const float* W2 = W2g + l * HIDv * HIDv;
    const float* b2 = b2g + l * HIDv;
    const float* W3 = W3g + l * HIDv * M3v;
    const float* b3 = b3g + l * M3v;

    for (int i = tid; i < HIDv * HIDv; i += NT) sm[OW2 + i] = W2[i];
    for (int i = tid; i < HIDv * M3v; i += NT) {
        int k = i / M3v, c = i - k * M3v;
        sm[OW3 + k * M3P + c] = W3[i];
    }
    for (int i = tid; i < M3v; i += NT) sm[OB3 + i] = b3[i];
    for (int i = tid; i < HIDv; i += NT) {
        sm[OB2 + i] = b2[i];
        sm[OB1 + i] = b1[i];
        sm[OWD + i] = W1[256 * 64 + i];
    }
    __syncthreads();

    int*   dstS = (int*)&sm[OMD];
    int*   srcS = (int*)&sm[OMS];
    float* Cs   = &sm[OMC];
    float* dds  = &sm[ODD];
    float* gvg  = &sm[OGV];

    for (int tile = blockIdx.x; tile < NTILES_E; tile += gridDim.x) {
        const int e0 = tile * TILE;
        const int ne = min(TILE, Ee - e0);

        if (tid < TILE) {
            if (tid < ne) {
                dstS[tid] = dst[e0 + tid];
                srcS[tid] = src[e0 + tid];
                float dd = dv[e0 + tid];
                dds[tid] = dd;
                Cs[tid] = (dd < 5.0f) ? 0.5f * (cosf(0.62831853071795864769f * dd) + 1.0f) : 0.0f;
            } else {
                dstS[tid] = 0; srcS[tid] = 0; Cs[tid] = 0.0f; dds[tid] = 0.0f;
            }
        }
        __syncthreads();

        // h1[e] = silu(P[dst] + Q[src] + d*wd + b1), batched LDG
        {
            const int ebase = w * 8;
            float wd0 = sm[OWD + lane], wd1 = sm[OWD + lane + 32];
            float bb0 = sm[OB1 + lane], bb1 = sm[OB1 + lane + 32];
            #pragma unroll
            for (int qb = 0; qb < 2; ++qb) {
                const int e4 = ebase + qb * 4;
                float P0[4], P1[4], Q0[4], Q1[4];
                #pragma unroll
                for (int j = 0; j < 4; ++j) {
                    const float* pp = &g_pq[(size_t)dstS[e4 + j] * 128];
                    const float* qq = &g_pq[(size_t)srcS[e4 + j] * 128 + 64];
                    P0[j] = pp[lane]; P1[j] = pp[lane + 32];
                    Q0[j] = qq[lane]; Q1[j] = qq[lane + 32];
                }
                #pragma unroll
                for (int j = 0; j < 4; ++j) {
                    int ee = e4 + j;
                    float de = dds[ee];
                    float h0  = P0[j] + Q0[j] + de * wd0 + bb0;
                    float h1v = P1[j] + Q1[j] + de * wd1 + bb1;
                    sm[OH1 + lane * TEP + ee]        = silu_f(h0);
                    sm[OH1 + (lane + 32) * TEP + ee] = silu_f(h1v);
                }
            }
        }
        __syncthreads();

        // ---- GEMM2: h2 = silu(h1 @ W2 + b2); overwrites H1 ----
        {
            u64 p0[4], p1[4];
            #pragma unroll
            for (int j = 0; j < 4; ++j) { p0[j] = 0ull; p1[j] = 0ull; }
            const int cb = 8 * w;
            #pragma unroll 4
            for (int k = 0; k < HIDv; ++k) {
                u64 A0 = splat2(sm[OH1 + k * TEP + lane]);
                u64 A1 = splat2(sm[OH1 + k * TEP + lane + 32]);
                const ulonglong2* wr = (const ulonglong2*)&sm[OW2 + k * HIDv + cb];
                ulonglong2 w0 = wr[0], w1 = wr[1];
                ffma2(p0[0], A0, w0.x); ffma2(p0[1], A0, w0.y);
                ffma2(p0[2], A0, w1.x); ffma2(p0[3], A0, w1.y);
                ffma2(p1[0], A1, w0.x); ffma2(p1[1], A1, w0.y);
                ffma2(p1[2], A1, w1.x); ffma2(p1[3], A1, w1.y);
            }
            __syncthreads();
            #pragma unroll
            for (int j = 0; j < 4; ++j) {
                float l0, h0, l1, h1;
                unpack2(p0[j], l0, h0); unpack2(p1[j], l1, h1);
                float ba = sm[OB2 + cb + 2*j], bbb = sm[OB2 + cb + 2*j + 1];
                sm[OH1 + (cb + 2*j)     * TEP + lane]      = silu_f(l0 + ba);
                sm[OH1 + (cb + 2*j + 1) * TEP + lane]      = silu_f(h0 + bbb);
                sm[OH1 + (cb + 2*j)     * TEP + lane + 32] = silu_f(l1 + ba);
                sm[OH1 + (cb + 2*j + 1) * TEP + lane + 32] = silu_f(h1 + bbb);
            }
        }
        __syncthreads();

        // ---- GEMM3 + gv/gr, coalesced scatter via transpose ----
        {
            u64 p0[8], p1[8];
            #pragma unroll
            for (int j = 0; j < 8; ++j) { p0[j] = 0ull; p1[j] = 0ull; }
            const int cb3 = 16 * w;
            #pragma unroll 2
            for (int k = 0; k < HIDv; ++k) {
                u64 A0 = splat2(sm[OH1 + k * TEP + lane]);
                u64 A1 = splat2(sm[OH1 + k * TEP + lane + 32]);
                const ulonglong2* wr = (const ulonglong2*)&sm[OW3 + k * M3P + cb3];
                ulonglong2 w0 = wr[0], w1 = wr[1], w2 = wr[2], w3 = wr[3];
                ffma2(p0[0], A0, w0.x); ffma2(p0[1], A0, w0.y);
                ffma2(p0[2], A0, w1.x); ffma2(p0[3], A0, w1.y);
                ffma2(p0[4], A0, w2.x); ffma2(p0[5], A0, w2.y);
                ffma2(p0[6], A0, w3.x); ffma2(p0[7], A0, w3.y);
                ffma2(p1[0], A1, w0.x); ffma2(p1[1], A1, w0.y);
                ffma2(p1[2], A1, w1.x); ffma2(p1[3], A1, w1.y);
                ffma2(p1[4], A1, w2.x); ffma2(p1[5], A1, w2.y);
                ffma2(p1[6], A1, w3.x); ffma2(p1[7], A1, w3.y);
            }

            if (w < 6) {
                float g0 = 0.0f, g1 = 0.0f;
                #pragma unroll 4
                for (int k = 0; k < HIDv; ++k) {
                    float ww = sm[OW3 + k * M3P + 128 + w];
                    g0 += sm[OH1 + k * TEP + lane] * ww;
                    g1 += sm[OH1 + k * TEP + lane + 32] * ww;
                }
                float bb = sm[OB3 + 128 + w];
                gvg[w * 64 + lane]      = g0 + bb;
                gvg[w * 64 + lane + 32] = g1 + bb;
            }

            float c0 = Cs[lane], c1 = Cs[lane + 32];
            float m0[16], m1[16];
            #pragma unroll
            for (int j = 0; j < 8; ++j) {
                unpack2(p0[j], m0[2*j], m0[2*j+1]);
                unpack2(p1[j], m1[2*j], m1[2*j+1]);
            }
            #pragma unroll
            for (int j = 0; j < 16; ++j) {
                float bb = sm[OB3 + cb3 + j];
                m0[j] = (m0[j] + bb) * c0;
                m1[j] = (m1[j] + bb) * c1;
            }
            __syncthreads();

            const int half0 = (w < 4) ? 0 : 1;
            const int cbh = cb3 - half0 * 64;

            // write h0 tiles
            if (half0 == 0) {
                float4* t0 = (float4*)&sm[OH1 + lane * TRS + cbh];
                float4* t1 = (float4*)&sm[OH1 + (lane + 32) * TRS + cbh];
                t0[0] = make_float4(m0[0], m0[1], m0[2], m0[3]);
                t0[1] = make_float4(m0[4], m0[5], m0[6], m0[7]);
                t0[2] = make_float4(m0[8], m0[9], m0[10], m0[11]);
                t0[3] = make_float4(m0[12], m0[13], m0[14], m0[15]);
                t1[0] = make_float4(m1[0], m1[1], m1[2], m1[3]);
                t1[1] = make_float4(m1[4], m1[5], m1[6], m1[7]);
                t1[2] = make_float4(m1[8], m1[9], m1[10], m1[11]);
                t1[3] = make_float4(m1[12], m1[13], m1[14], m1[15]);
            }
            __syncthreads();
            #pragma unroll
            for (int it = 0; it < 4; ++it) {
                int e = w * 8 + it * 2 + (lane >> 4);
                int c4 = (lane & 15) * 4;
                float4 val = *(const float4*)&sm[OH1 + e * TRS + c4];
                float* bp = &g_sagg[(size_t)dstS[e] * SDv + c4];
                red4(bp, val.x, val.y, val.z, val.w);
            }
            __syncthreads();
            // write h1 tiles
            if (half0 == 1) {
                float4* t0 = (float4*)&sm[OH1 + lane * TRS + cbh];
                float4* t1 = (float4*)&sm[OH1 + (lane + 32) * TRS + cbh];
                t0[0] = make_float4(m0[0], m0[1], m0[2], m0[3]);
                t0[1] = make_float4(m0[4], m0[5], m0[6], m0[7]);
                t0[2] = make_float4(m0[8], m0[9], m0[10], m0[11]);
                t0[3] = make_float4(m0[12], m0[13], m0[14], m0[15]);
                t1[0] = make_float4(m1[0], m1[1], m1[2], m1[3]);
                t1[1] = make_float4(m1[4], m1[5], m1[6], m1[7]);
                t1[2] = make_float4(m1[8], m1[9], m1[10], m1[11]);
                t1[3] = make_float4(m1[12], m1[13], m1[14], m1[15]);
            }
            __syncthreads();
            #pragma unroll
            for (int it = 0; it < 4; ++it) {
                int e = w * 8 + it * 2 + (lane >> 4);
                int c4 = (lane & 15) * 4;
                float4 val = *(const float4*)&sm[OH1 + e * TRS + c4];
                float* bp = &g_sagg[(size_t)dstS[e] * SDv + 64 + c4];
                red4(bp, val.x, val.y, val.z, val.w);
            }
            // NOTE: no sync here — vm scatter below doesn't touch OH1; next-tile
            // writes to OH1/metadata are gated by the vm-scatter-end barrier.
        }

        // vm scatter
        for (int idx = tid; idx < 9 * TILE; idx += NT) {
            int e = idx / 9;
            if (e >= ne) break;
            int c = idx - e * 9;
            int i3 = c / 3, j3 = c - i3 * 3;
            int se = srcS[e], de = dstS[e];
            float val = (g_v[(size_t)se * 9 + c] * gvg[i3 * 64 + e]
                       + rv[(size_t)(e0 + e) * 3 + j3] * gvg[(3 + i3) * 64 + e]) * Cs[e];
            atomicAdd(&g_vagg[(size_t)de * 9 + c], val);
        }
        __syncthreads();
    }
}

// -------------------- fused node kernel (monolithic, 1 CTA/SM) --------------------
__global__ void __launch_bounds__(NT, 1)
k_node(const float* __restrict__ Wn1g, const float* __restrict__ bn1g,
       const float* __restrict__ Wn2g, const float* __restrict__ bn2g,
       float* __restrict__ outp, int last, int l)
{
    extern __shared__ float sm[];
    const int tid = threadIdx.x;
    const int w = tid >> 5, lane = tid & 31;

    const float* Wn1 = Wn1g + (size_t)l * 2 * SDv * HIDv;
    const float* bn1 = bn1g + l * HIDv;
    const float* Wn2 = Wn2g + (size_t)l * HIDv * SDv;
    const float* bn2 = bn2g + l * SDv;

    for (int i = tid; i < 2 * SDv * HIDv; i += NT) sm[OWn1 + i] = Wn1[i];
    for (int i = tid; i < HIDv; i += NT) sm[OBn1 + i] = bn1[i];
    for (int i = tid; i < HIDv * SDv; i += NT) sm[OWn2 + i] = Wn2[i];
    for (int i = tid; i < SDv; i += NT) sm[OBn2 + i] = bn2[i];
    __syncthreads();

    float* out_s = outp;
    float* out_v = outp + (size_t)Nn * SDv;

    for (int tile = blockIdx.x; tile < NTILES_N; tile += gridDim.x) {
        const int n0 = tile * TILE;
        const int nn = min(TILE, Nn - n0);

        #pragma unroll 4
        for (int i = tid; i < TILE * SDv; i += NT) {
            int n = i >> 7, k = i & 127;
            float a = 0.0f, b = 0.0f;
            if (n < nn) {
                a = g_s[(size_t)(n0 + n) * SDv + k];
                b = g_sagg[(size_t)(n0 + n) * SDv + k];
            }
            sm[OX + k * TEP + n]         = a;
            sm[OX + (128 + k) * TEP + n] = b;
        }
        __syncthreads();

        // GEMM A: u = silu(x @ Wn1 + bn1), K=256
        {
            u64 p0[4], p1[4];
            #pragma unroll
            for (int j = 0; j < 4; ++j) { p0[j] = 0ull; p1[j] = 0ull; }
            const int cb = 8 * w;
            #pragma unroll 4
            for (int k = 0; k < 2 * SDv; ++k) {
                u64 A0 = splat2(sm[OX + k * TEP + lane]);
                u64 A1 = splat2(sm[OX + k * TEP + lane + 32]);
                const ulonglong2* wr = (const ulonglong2*)&sm[OWn1 + k * HIDv + cb];
                ulonglong2 w0 = wr[0], w1 = wr[1];
                ffma2(p0[0], A0, w0.x); ffma2(p0[1], A0, w0.y);
                ffma2(p0[2], A0, w1.x); ffma2(p0[3], A0, w1.y);
                ffma2(p1[0], A1, w0.x); ffma2(p1[1], A1, w0.y);
                ffma2(p1[2], A1, w1.x); ffma2(p1[3], A1, w1.y);
            }
            #pragma unroll
            for (int j = 0; j < 4; ++j) {
                float l0, h0, l1, h1;
                unpack2(p0[j], l0, h0); unpack2(p1[j], l1, h1);
                float ba = sm[OBn1 + cb + 2*j], bbb = sm[OBn1 + cb + 2*j + 1];
                sm[OU + (cb + 2*j)     * TEP + lane]      = silu_f(l0 + ba);
                sm[OU + (cb + 2*j + 1) * TEP + lane]      = silu_f(h0 + bbb);
                sm[OU + (cb + 2*j)     * TEP + lane + 32] = silu_f(l1 + ba);
                sm[OU + (cb + 2*j + 1) * TEP + lane + 32] = silu_f(h1 + bbb);
            }
        }
        __syncthreads();

        // GEMM B: s_new = s + u @ Wn2 + bn2
        {
            u64 p0[8], p1[8];
            #pragma unroll
            for (int j = 0; j < 8; ++j) { p0[j] = 0ull; p1[j] = 0ull; }
            const int cb3 = 16 * w;
            #pragma unroll 2
            for (int k = 0; k < HIDv; ++k) {
                u64 A0 = splat2(sm[OU + k * TEP + lane]);
                u64 A1 = splat2(sm[OU + k * TEP + lane + 32]);
                const ulonglong2* wr = (const ulonglong2*)&sm[OWn2 + k * SDv + cb3];
                ulonglong2 w0 = wr[0], w1 = wr[1], w2 = wr[2], w3 = wr[3];
                ffma2(p0[0], A0, w0.x); ffma2(p0[1], A0, w0.y);
                ffma2(p0[2], A0, w1.x); ffma2(p0[3], A0, w1.y);
                ffma2(p0[4], A0, w2.x); ffma2(p0[5], A0, w2.y);
                ffma2(p0[6], A0, w3.x); ffma2(p0[7], A0, w3.y);
                ffma2(p1[0], A1, w0.x); ffma2(p1[1], A1, w0.y);
                ffma2(p1[2], A1, w1.x); ffma2(p1[3], A1, w1.y);
                ffma2(p1[4], A1, w2.x); ffma2(p1[5], A1, w2.y);
                ffma2(p1[6], A1, w3.x); ffma2(p1[7], A1, w3.y);
            }
            float m0[16], m1[16];
            #pragma unroll
            for (int j = 0; j < 8; ++j) {
                unpack2(p0[j], m0[2*j], m0[2*j+1]);
                unpack2(p1[j], m1[2*j], m1[2*j+1]);
            }
            float* dst_s = last ? out_s : g_s;
            if (lane < nn) {
                float4* srow = (float4*)&dst_s[(size_t)(n0 + lane) * SDv + cb3];
                #pragma unroll
                for (int j4 = 0; j4 < 4; ++j4) {
                    float4 vv;
                    vv.x = sm[OX + (cb3 + 4*j4 + 0) * TEP + lane] + m0[4*j4 + 0] + sm[OBn2 + cb3 + 4*j4 + 0];
                    vv.y = sm[OX + (cb3 + 4*j4 + 1) * TEP + lane] + m0[4*j4 + 1] + sm[OBn2 + cb3 + 4*j4 + 1];
                    vv.z = sm[OX + (cb3 + 4*j4 + 2) * TEP + lane] + m0[4*j4 + 2] + sm[OBn2 + cb3 + 4*j4 + 2];
                    vv.w = sm[OX + (cb3 + 4*j4 + 3) * TEP + lane] + m0[4*j4 + 3] + sm[OBn2 + cb3 + 4*j4 + 3];
                    srow[j4] = vv;
                }
            }
            if (lane + 32 < nn) {
                float4* srow = (float4*)&dst_s[(size_t)(n0 + lane + 32) * SDv + cb3];
                #pragma unroll
                for (int j4 = 0; j4 < 4; ++j4) {
                    float4 vv;
                    vv.x = sm[OX + (cb3 + 4*j4 + 0) * TEP + lane + 32] + m1[4*j4 + 0] + sm[OBn2 + cb3 + 4*j4 + 0];
                    vv.y = sm[OX + (cb3 + 4*j4 + 1) * TEP + lane + 32] + m1[4*j4 + 1] + sm[OBn2 + cb3 + 4*j4 + 1];
                    vv.z = sm[OX + (cb3 + 4*j4 + 2) * TEP + lane + 32] + m1[4*j4 + 2] + sm[OBn2 + cb3 + 4*j4 + 2];
                    vv.w = sm[OX + (cb3 + 4*j4 + 3) * TEP + lane + 32] + m1[4*j4 + 3] + sm[OBn2 + cb3 + 4*j4 + 3];
                    srow[j4] = vv;
                }
            }
        }

        // v update
        for (int idx = tid; idx < 9 * TILE; idx += NT) {
            int nl = idx / 9;
            if (nl >= nn) break;
            int c = idx - nl * 9;
            int n = n0 + nl;
            float nv = g_v[(size_t)n * 9 + c] + g_vagg[(size_t)n * 9 + c] * g_inv[n];
            if (last) out_v[(size_t)n * 9 + c] = nv;
            else      g_v[(size_t)n * 9 + c] = nv;
        }
        __syncthreads();
    }
}

// -------------------- launch --------------------
extern "C" void kernel_launch(void* const* d_in, const int* in_sizes, int n_in,
                              void* d_out, int out_size)
{
    const float* s   = (const float*)d_in[0];
    const float* v   = (const float*)d_in[1];
    const int*   ei  = (const int*)d_in[2];
    const float* dv  = (const float*)d_in[3];
    const float* rv  = (const float*)d_in[4];
    const float* W1  = (const float*)d_in[5];
    const float* b1  = (const float*)d_in[6];
    const float* W2  = (const float*)d_in[7];
    const float* b2  = (const float*)d_in[8];
    const float* W3  = (const float*)d_in[9];
    const float* b3  = (const float*)d_in[10];
    const float* Wn1 = (const float*)d_in[11];
    const float* bn1 = (const float*)d_in[12];
    const float* Wn2 = (const float*)d_in[13];
    const float* bn2 = (const float*)d_in[14];
    const int* dst = ei;
    const int* src = ei + Ee;
    float* outp = (float*)d_out;

    cudaFuncSetAttribute(k_edge, cudaFuncAttributeMaxDynamicSharedMemorySize, SME_BYTES);
    cudaFuncSetAttribute(k_pq,   cudaFuncAttributeMaxDynamicSharedMemorySize, SMP_BYTES);
    cudaFuncSetAttribute(k_node, cudaFuncAttributeMaxDynamicSharedMemorySize, SMN_BYTES);

    k_init<<<(Nn * SDv + 255) / 256, 256>>>(s, v);
    k_pq<<<888, NT, SMP_BYTES>>>(W1, 0);
    k_count<<<(Ee + 255) / 256, 256>>>(dst);
    k_edge<<<444, NT, SME_BYTES>>>(dst, src, dv, rv, W1, b1, W2, b2, W3, b3, 0);
    k_inv<<<(Nn + 255) / 256, 256>>>();
    k_node<<<148, NT, SMN_BYTES>>>(Wn1, bn1, Wn2, bn2, outp, 0, 0);

    for (int l = 1; l < 4; ++l) {
        k_pq<<<888, NT, SMP_BYTES>>>(W1, l);
        k_edge<<<444, NT, SME_BYTES>>>(dst, src, dv, rv, W1, b1, W2, b2, W3, b3, l);
        k_node<<<148, NT, SMN_BYTES>>>(Wn1, bn1, Wn2, bn2, outp, (l == 3) ? 1 : 0, l);
    }
}

// round 13
// speedup vs baseline: 1.5803x; 1.5803x over previous
#include <cuda_runtime.h>
#include <math.h>

#define Nn   50000
#define Ee   500000
#define SDv  128
#define HIDv 64
#define K1v  257
#define M3v  134
#define M3P  136
#define TILE 64
#define TEP  65
#define TRS  68
#define NT   256
#define NTILES_E ((Ee + TILE - 1) / TILE)
#define NTILES_N ((Nn + TILE - 1) / TILE)

// ---- edge-kernel shared memory ----
#define OW2 0
#define OB2 (OW2 + HIDv*HIDv)
#define OW3 (OB2 + HIDv)
#define OB3 (OW3 + HIDv*M3P)
#define OWD (OB3 + M3P)
#define OB1 (OWD + HIDv)
#define OH1 (OB1 + HIDv)
#define OMD (OH1 + TILE*TRS)
#define OMS (OMD + TILE)
#define OMC (OMS + TILE)
#define ODD (OMC + TILE)
#define OGV (ODD + TILE)
#define SME_FLOATS (OGV + 6*TILE)
#define SME_BYTES (SME_FLOATS * 4)     // ~72.5 KB -> 3 CTAs/SM

// ---- PQ kernel smem (column-split halves) ----
#define OWh 0
#define OXh (OWh + 128*64)
#define SMP_FLOATS (OXh + SDv*TEP)
#define SMP_BYTES (SMP_FLOATS * 4)     // ~66 KB -> 3 CTAs/SM

// ---- node kernel smem (all weights in smem, 1 CTA/SM) ----
#define OWn1 0
#define OBn1 (OWn1 + 2*SDv*HIDv)
#define OWn2 (OBn1 + HIDv)
#define OBn2 (OWn2 + HIDv*SDv)
#define OX   (OBn2 + SDv)
#define OU   (OX + 2*SDv*TEP)
#define SMN_FLOATS (OU + HIDv*TEP)
#define SMN_BYTES (SMN_FLOATS * 4)

__device__ float g_s[(size_t)Nn * SDv];
__device__ float g_v[(size_t)Nn * 9];
__device__ float g_sagg[(size_t)Nn * SDv];
__device__ float g_vagg[(size_t)Nn * 9];
__device__ float g_pq[(size_t)Nn * 128];
__device__ float g_cnt[Nn];
__device__ float g_inv[Nn];

typedef unsigned long long u64;

__device__ __forceinline__ float silu_f(float x) { return x / (1.0f + __expf(-x)); }

__device__ __forceinline__ void red4(float* p, float a, float b, float c, float d) {
    asm volatile("red.global.add.v4.f32 [%0], {%1,%2,%3,%4};"
                 :: "l"(p), "f"(a), "f"(b), "f"(c), "f"(d) : "memory");
}
__device__ __forceinline__ u64 splat2(float a) {
    u64 r; asm("mov.b64 %0, {%1, %1};" : "=l"(r) : "f"(a)); return r;
}
__device__ __forceinline__ void ffma2(u64& acc, u64 a2, u64 w2) {
    asm("fma.rn.f32x2 %0, %1, %2, %0;" : "+l"(acc) : "l"(a2), "l"(w2));
}
__device__ __forceinline__ void unpack2(u64 p, float& lo, float& hi) {
    asm("mov.b64 {%0, %1}, %2;" : "=f"(lo), "=f"(hi) : "l"(p));
}

// -------------------- init / misc --------------------
__global__ void k_init(const float* __restrict__ s, const float* __restrict__ v) {
    int i = blockIdx.x * blockDim.x + threadIdx.x;
    if (i < Nn * SDv) g_s[i] = s[i];
    if (i < Nn * 9)   g_v[i] = v[i];
    if (i < Nn)       g_cnt[i] = 0.0f;
}
__global__ void k_count(const int* __restrict__ dst) {
    int e = blockIdx.x * blockDim.x + threadIdx.x;
    if (e < Ee) atomicAdd(&g_cnt[dst[e]], 1.0f);
}
__global__ void k_inv() {
    int i = blockIdx.x * blockDim.x + threadIdx.x;
    if (i < Nn) g_inv[i] = 1.0f / fmaxf(g_cnt[i], 1.0f);
}

// -------------------- PQ precompute (column-split, 3 CTAs/SM, + zero agg) --------------------
__global__ void __launch_bounds__(NT, 3)
k_pq(const float* __restrict__ W1g, int l)
{
    extern __shared__ float sm[];
    const int tid = threadIdx.x;
    const int w = tid >> 5, lane = tid & 31;
    const float* W1 = W1g + (size_t)l * K1v * HIDv;
    const int half = blockIdx.x & 1;
    const float* Wh = W1 + half * 128 * 64;

    for (int i = blockIdx.x * NT + tid; i < Nn * SDv; i += gridDim.x * NT) g_sagg[i] = 0.0f;
    for (int i = blockIdx.x * NT + tid; i < Nn * 9; i += gridDim.x * NT) g_vagg[i] = 0.0f;

    for (int i = tid; i < 128 * 64; i += NT) sm[OWh + i] = Wh[i];
    __syncthreads();

    const int tstep = gridDim.x >> 1;
    for (int tile = (blockIdx.x >> 1); tile < NTILES_N; tile += tstep) {
        const int n0 = tile * TILE;
        const int nn = min(TILE, Nn - n0);

        #pragma unroll 4
        for (int i = tid; i < TILE * SDv; i += NT) {
            int n = i >> 7, k = i & 127;
            sm[OXh + k * TEP + n] = (n < nn) ? g_s[(size_t)(n0 + n) * SDv + k] : 0.0f;
        }
        __syncthreads();

        {
            u64 p0[4], p1[4];
            #pragma unroll
            for (int j = 0; j < 4; ++j) { p0[j] = 0ull; p1[j] = 0ull; }
            const int cb = 8 * w;
            #pragma unroll 4
            for (int k = 0; k < 128; ++k) {
                u64 A0 = splat2(sm[OXh + k * TEP + lane]);
                u64 A1 = splat2(sm[OXh + k * TEP + lane + 32]);
                const ulonglong2* wr = (const ulonglong2*)&sm[OWh + k * 64 + cb];
                ulonglong2 w0 = wr[0], w1 = wr[1];
                ffma2(p0[0], A0, w0.x); ffma2(p0[1], A0, w0.y);
                ffma2(p0[2], A0, w1.x); ffma2(p0[3], A0, w1.y);
                ffma2(p1[0], A1, w0.x); ffma2(p1[1], A1, w0.y);
                ffma2(p1[2], A1, w1.x); ffma2(p1[3], A1, w1.y);
            }
            if (lane < nn) {
                float4* op = (float4*)&g_pq[(size_t)(n0 + lane) * 128 + half * 64 + cb];
                float o0, o1, o2, o3, o4, o5, o6, o7;
                unpack2(p0[0], o0, o1); unpack2(p0[1], o2, o3);
                unpack2(p0[2], o4, o5); unpack2(p0[3], o6, o7);
                op[0] = make_float4(o0, o1, o2, o3);
                op[1] = make_float4(o4, o5, o6, o7);
            }
            if (lane + 32 < nn) {
                float4* op = (float4*)&g_pq[(size_t)(n0 + lane + 32) * 128 + half * 64 + cb];
                float o0, o1, o2, o3, o4, o5, o6, o7;
                unpack2(p1[0], o0, o1); unpack2(p1[1], o2, o3);
                unpack2(p1[2], o4, o5); unpack2(p1[3], o6, o7);
                op[0] = make_float4(o0, o1, o2, o3);
                op[1] = make_float4(o4, o5, o6, o7);
            }
        }
        __syncthreads();
    }
}

// -------------------- fused edge kernel (R8) --------------------
__global__ void __launch_bounds__(NT, 3)
k_edge(const int* __restrict__ dst, const int* __restrict__ src,
       const float* __restrict__ dv, const float* __restrict__ rv,
       const float* __restrict__ W1g, const float* __restrict__ b1g,
       const float* __restrict__ W2g, const float* __restrict__ b2g,
       const float* __restrict__ W3g, const float* __restrict__ b3g,
       int l)
{
    extern __shared__ float sm[];
    const int tid = threadIdx.x;
    const int w = tid >> 5, lane = tid & 31;

    const float* W1 = W1g + (size_t)l * K1v * HIDv;
    const float* b1 = b1g + l * HIDv;
    const float* W2 = W2g + l * HIDv * HIDv;
    const float* b2 = b2g + l * HIDv;
    const float* W3 = W3g + l * HIDv * M3v;
    const float* b3 = b3g + l * M3v;

    for (int i = tid; i < HIDv * HIDv; i += NT) sm[OW2 + i] = W2[i];
    for (int i = tid; i < HIDv * M3v; i += NT) {
        int k = i / M3v, c = i - k * M3v;
        sm[OW3 + k * M3P + c] = W3[i];
    }
    for (int i = tid; i < M3v; i += NT) sm[OB3 + i] = b3[i];
    for (int i = tid; i < HIDv; i += NT) {
        sm[OB2 + i] = b2[i];
        sm[OB1 + i] = b1[i];
        sm[OWD + i] = W1[256 * 64 + i];
    }
    __syncthreads();

    int*   dstS = (int*)&sm[OMD];
    int*   srcS = (int*)&sm[OMS];
    float* Cs   = &sm[OMC];
    float* dds  = &sm[ODD];
    float* gvg  = &sm[OGV];

    for (int tile = blockIdx.x; tile < NTILES_E; tile += gridDim.x) {
        const int e0 = tile * TILE;
        const int ne = min(TILE, Ee - e0);

        if (tid < TILE) {
            if (tid < ne) {
                dstS[tid] = dst[e0 + tid];
                srcS[tid] = src[e0 + tid];
                float dd = dv[e0 + tid];
                dds[tid] = dd;
                Cs[tid] = (dd < 5.0f) ? 0.5f * (cosf(0.62831853071795864769f * dd) + 1.0f) : 0.0f;
            } else {
                dstS[tid] = 0; srcS[tid] = 0; Cs[tid] = 0.0f; dds[tid] = 0.0f;
            }
        }
        __syncthreads();

        // h1[e] = silu(P[dst] + Q[src] + d*wd + b1), batched LDG
        {
            const int ebase = w * 8;
            float wd0 = sm[OWD + lane], wd1 = sm[OWD + lane + 32];
            float bb0 = sm[OB1 + lane], bb1 = sm[OB1 + lane + 32];
            #pragma unroll
            for (int qb = 0; qb < 2; ++qb) {
                const int e4 = ebase + qb * 4;
                float P0[4], P1[4], Q0[4], Q1[4];
                #pragma unroll
                for (int j = 0; j < 4; ++j) {
                    const float* pp = &g_pq[(size_t)dstS[e4 + j] * 128];
                    const float* qq = &g_pq[(size_t)srcS[e4 + j] * 128 + 64];
                    P0[j] = pp[lane]; P1[j] = pp[lane + 32];
                    Q0[j] = qq[lane]; Q1[j] = qq[lane + 32];
                }
                #pragma unroll
                for (int j = 0; j < 4; ++j) {
                    int ee = e4 + j;
                    float de = dds[ee];
                    float h0  = P0[j] + Q0[j] + de * wd0 + bb0;
                    float h1v = P1[j] + Q1[j] + de * wd1 + bb1;
                    sm[OH1 + lane * TEP + ee]        = silu_f(h0);
                    sm[OH1 + (lane + 32) * TEP + ee] = silu_f(h1v);
                }
            }
        }
        __syncthreads();

        // ---- GEMM2: h2 = silu(h1 @ W2 + b2); overwrites H1 ----
        {
            u64 p0[4], p1[4];
            #pragma unroll
            for (int j = 0; j < 4; ++j) { p0[j] = 0ull; p1[j] = 0ull; }
            const int cb = 8 * w;
            #pragma unroll 4
            for (int k = 0; k < HIDv; ++k) {
                u64 A0 = splat2(sm[OH1 + k * TEP + lane]);
                u64 A1 = splat2(sm[OH1 + k * TEP + lane + 32]);
                const ulonglong2* wr = (const ulonglong2*)&sm[OW2 + k * HIDv + cb];
                ulonglong2 w0 = wr[0], w1 = wr[1];
                ffma2(p0[0], A0, w0.x); ffma2(p0[1], A0, w0.y);
                ffma2(p0[2], A0, w1.x); ffma2(p0[3], A0, w1.y);
                ffma2(p1[0], A1, w0.x); ffma2(p1[1], A1, w0.y);
                ffma2(p1[2], A1, w1.x); ffma2(p1[3], A1, w1.y);
            }
            __syncthreads();
            #pragma unroll
            for (int j = 0; j < 4; ++j) {
                float l0, h0, l1, h1;
                unpack2(p0[j], l0, h0); unpack2(p1[j], l1, h1);
                float ba = sm[OB2 + cb + 2*j], bbb = sm[OB2 + cb + 2*j + 1];
                sm[OH1 + (cb + 2*j)     * TEP + lane]      = silu_f(l0 + ba);
                sm[OH1 + (cb + 2*j + 1) * TEP + lane]      = silu_f(h0 + bbb);
                sm[OH1 + (cb + 2*j)     * TEP + lane + 32] = silu_f(l1 + ba);
                sm[OH1 + (cb + 2*j + 1) * TEP + lane + 32] = silu_f(h1 + bbb);
            }
        }
        __syncthreads();

        // ---- GEMM3 + gv/gr, coalesced scatter via smem transpose ----
        {
            u64 p0[8], p1[8];
            #pragma unroll
            for (int j = 0; j < 8; ++j) { p0[j] = 0ull; p1[j] = 0ull; }
            const int cb3 = 16 * w;
            #pragma unroll 2
            for (int k = 0; k < HIDv; ++k) {
                u64 A0 = splat2(sm[OH1 + k * TEP + lane]);
                u64 A1 = splat2(sm[OH1 + k * TEP + lane + 32]);
                const ulonglong2* wr = (const ulonglong2*)&sm[OW3 + k * M3P + cb3];
                ulonglong2 w0 = wr[0], w1 = wr[1], w2 = wr[2], w3 = wr[3];
                ffma2(p0[0], A0, w0.x); ffma2(p0[1], A0, w0.y);
                ffma2(p0[2], A0, w1.x); ffma2(p0[3], A0, w1.y);
                ffma2(p0[4], A0, w2.x); ffma2(p0[5], A0, w2.y);
                ffma2(p0[6], A0, w3.x); ffma2(p0[7], A0, w3.y);
                ffma2(p1[0], A1, w0.x); ffma2(p1[1], A1, w0.y);
                ffma2(p1[2], A1, w1.x); ffma2(p1[3], A1, w1.y);
                ffma2(p1[4], A1, w2.x); ffma2(p1[5], A1, w2.y);
                ffma2(p1[6], A1, w3.x); ffma2(p1[7], A1, w3.y);
            }

            if (w < 6) {
                float g0 = 0.0f, g1 = 0.0f;
                #pragma unroll 4
                for (int k = 0; k < HIDv; ++k) {
                    float ww = sm[OW3 + k * M3P + 128 + w];
                    g0 += sm[OH1 + k * TEP + lane] * ww;
                    g1 += sm[OH1 + k * TEP + lane + 32] * ww;
                }
                float bb = sm[OB3 + 128 + w];
                gvg[w * 64 + lane]      = g0 + bb;
                gvg[w * 64 + lane + 32] = g1 + bb;
            }

            float c0 = Cs[lane], c1 = Cs[lane + 32];
            float m0[16], m1[16];
            #pragma unroll
            for (int j = 0; j < 8; ++j) {
                unpack2(p0[j], m0[2*j], m0[2*j+1]);
                unpack2(p1[j], m1[2*j], m1[2*j+1]);
            }
            #pragma unroll
            for (int j = 0; j < 16; ++j) {
                float bb = sm[OB3 + cb3 + j];
                m0[j] = (m0[j] + bb) * c0;
                m1[j] = (m1[j] + bb) * c1;
            }
            __syncthreads();

            const int half0 = (w < 4) ? 0 : 1;
            const int cbh = cb3 - half0 * 64;

            #pragma unroll
            for (int half = 0; half < 2; ++half) {
                if (half0 == half) {
                    float4* t0 = (float4*)&sm[OH1 + lane * TRS + cbh];
                    float4* t1 = (float4*)&sm[OH1 + (lane + 32) * TRS + cbh];
                    t0[0] = make_float4(m0[0], m0[1], m0[2], m0[3]);
                    t0[1] = make_float4(m0[4], m0[5], m0[6], m0[7]);
                    t0[2] = make_float4(m0[8], m0[9], m0[10], m0[11]);
                    t0[3] = make_float4(m0[12], m0[13], m0[14], m0[15]);
                    t1[0] = make_float4(m1[0], m1[1], m1[2], m1[3]);
                    t1[1] = make_float4(m1[4], m1[5], m1[6], m1[7]);
                    t1[2] = make_float4(m1[8], m1[9], m1[10], m1[11]);
                    t1[3] = make_float4(m1[12], m1[13], m1[14], m1[15]);
                }
                __syncthreads();
                #pragma unroll
                for (int it = 0; it < 4; ++it) {
                    int e = w * 8 + it * 2 + (lane >> 4);
                    int c4 = (lane & 15) * 4;
                    float4 val = *(const float4*)&sm[OH1 + e * TRS + c4];
                    float* bp = &g_sagg[(size_t)dstS[e] * SDv + half * 64 + c4];
                    red4(bp, val.x, val.y, val.z, val.w);
                }
                __syncthreads();
            }
        }

        // vm scatter
        for (int idx = tid; idx < 9 * TILE; idx += NT) {
            int e = idx / 9;
            if (e >= ne) break;
            int c = idx - e * 9;
            int i3 = c / 3, j3 = c - i3 * 3;
            int se = srcS[e], de = dstS[e];
            float val = (g_v[(size_t)se * 9 + c] * gvg[i3 * 64 + e]
                       + rv[(size_t)(e0 + e) * 3 + j3] * gvg[(3 + i3) * 64 + e]) * Cs[e];
            atomicAdd(&g_vagg[(size_t)de * 9 + c], val);
        }
        __syncthreads();
    }
}

// -------------------- fused node kernel (R8 monolithic, 1 CTA/SM) --------------------
__global__ void __launch_bounds__(NT, 1)
k_node(const float* __restrict__ Wn1g, const float* __restrict__ bn1g,
       const float* __restrict__ Wn2g, const float* __restrict__ bn2g,
       float* __restrict__ outp, int last, int l)
{
    extern __shared__ float sm[];
    const int tid = threadIdx.x;
    const int w = tid >> 5, lane = tid & 31;

    const float* Wn1 = Wn1g + (size_t)l * 2 * SDv * HIDv;
    const float* bn1 = bn1g + l * HIDv;
    const float* Wn2 = Wn2g + (size_t)l * HIDv * SDv;
    const float* bn2 = bn2g + l * SDv;

    for (int i = tid; i < 2 * SDv * HIDv; i += NT) sm[OWn1 + i] = Wn1[i];
    for (int i = tid; i < HIDv; i += NT) sm[OBn1 + i] = bn1[i];
    for (int i = tid; i < HIDv * SDv; i += NT) sm[OWn2 + i] = Wn2[i];
    for (int i = tid; i < SDv; i += NT) sm[OBn2 + i] = bn2[i];
    __syncthreads();

    float* out_s = outp;
    float* out_v = outp + (size_t)Nn * SDv;

    for (int tile = blockIdx.x; tile < NTILES_N; tile += gridDim.x) {
        const int n0 = tile * TILE;
        const int nn = min(TILE, Nn - n0);

        #pragma unroll 4
        for (int i = tid; i < TILE * SDv; i += NT) {
            int n = i >> 7, k = i & 127;
            float a = 0.0f, b = 0.0f;
            if (n < nn) {
                a = g_s[(size_t)(n0 + n) * SDv + k];
                b = g_sagg[(size_t)(n0 + n) * SDv + k];
            }
            sm[OX + k * TEP + n]         = a;
            sm[OX + (128 + k) * TEP + n] = b;
        }
        __syncthreads();

        // GEMM A: u = silu(x @ Wn1 + bn1), K=256
        {
            u64 p0[4], p1[4];
            #pragma unroll
            for (int j = 0; j < 4; ++j) { p0[j] = 0ull; p1[j] = 0ull; }
            const int cb = 8 * w;
            #pragma unroll 4
            for (int k = 0; k < 2 * SDv; ++k) {
                u64 A0 = splat2(sm[OX + k * TEP + lane]);
                u64 A1 = splat2(sm[OX + k * TEP + lane + 32]);
                const ulonglong2* wr = (const ulonglong2*)&sm[OWn1 + k * HIDv + cb];
                ulonglong2 w0 = wr[0], w1 = wr[1];
                ffma2(p0[0], A0, w0.x); ffma2(p0[1], A0, w0.y);
                ffma2(p0[2], A0, w1.x); ffma2(p0[3], A0, w1.y);
                ffma2(p1[0], A1, w0.x); ffma2(p1[1], A1, w0.y);
                ffma2(p1[2], A1, w1.x); ffma2(p1[3], A1, w1.y);
            }
            #pragma unroll
            for (int j = 0; j < 4; ++j) {
                float l0, h0, l1, h1;
                unpack2(p0[j], l0, h0); unpack2(p1[j], l1, h1);
                float ba = sm[OBn1 + cb + 2*j], bbb = sm[OBn1 + cb + 2*j + 1];
                sm[OU + (cb + 2*j)     * TEP + lane]      = silu_f(l0 + ba);
                sm[OU + (cb + 2*j + 1) * TEP + lane]      = silu_f(h0 + bbb);
                sm[OU + (cb + 2*j)     * TEP + lane + 32] = silu_f(l1 + ba);
                sm[OU + (cb + 2*j + 1) * TEP + lane + 32] = silu_f(h1 + bbb);
            }
        }
        __syncthreads();

        // GEMM B: s_new = s + u @ Wn2 + bn2
        {
            u64 p0[8], p1[8];
            #pragma unroll
            for (int j = 0; j < 8; ++j) { p0[j] = 0ull; p1[j] = 0ull; }
            const int cb3 = 16 * w;
            #pragma unroll 2
            for (int k = 0; k < HIDv; ++k) {
                u64 A0 = splat2(sm[OU + k * TEP + lane]);
                u64 A1 = splat2(sm[OU + k * TEP + lane + 32]);
                const ulonglong2* wr = (const ulonglong2*)&sm[OWn2 + k * SDv + cb3];
                ulonglong2 w0 = wr[0], w1 = wr[1], w2 = wr[2], w3 = wr[3];
                ffma2(p0[0], A0, w0.x); ffma2(p0[1], A0, w0.y);
                ffma2(p0[2], A0, w1.x); ffma2(p0[3], A0, w1.y);
                ffma2(p0[4], A0, w2.x); ffma2(p0[5], A0, w2.y);
                ffma2(p0[6], A0, w3.x); ffma2(p0[7], A0, w3.y);
                ffma2(p1[0], A1, w0.x); ffma2(p1[1], A1, w0.y);
                ffma2(p1[2], A1, w1.x); ffma2(p1[3], A1, w1.y);
                ffma2(p1[4], A1, w2.x); ffma2(p1[5], A1, w2.y);
                ffma2(p1[6], A1, w3.x); ffma2(p1[7], A1, w3.y);
            }
            float m0[16], m1[16];
            #pragma unroll
            for (int j = 0; j < 8; ++j) {
                unpack2(p0[j], m0[2*j], m0[2*j+1]);
                unpack2(p1[j], m1[2*j], m1[2*j+1]);
            }
            float* dst_s = last ? out_s : g_s;
            if (lane < nn) {
                float4* srow = (float4*)&dst_s[(size_t)(n0 + lane) * SDv + cb3];
                #pragma unroll
                for (int j4 = 0; j4 < 4; ++j4) {
                    float4 vv;
                    vv.x = sm[OX + (cb3 + 4*j4 + 0) * TEP + lane] + m0[4*j4 + 0] + sm[OBn2 + cb3 + 4*j4 + 0];
                    vv.y = sm[OX + (cb3 + 4*j4 + 1) * TEP + lane] + m0[4*j4 + 1] + sm[OBn2 + cb3 + 4*j4 + 1];
                    vv.z = sm[OX + (cb3 + 4*j4 + 2) * TEP + lane] + m0[4*j4 + 2] + sm[OBn2 + cb3 + 4*j4 + 2];
                    vv.w = sm[OX + (cb3 + 4*j4 + 3) * TEP + lane] + m0[4*j4 + 3] + sm[OBn2 + cb3 + 4*j4 + 3];
                    srow[j4] = vv;
                }
            }
            if (lane + 32 < nn) {
                float4* srow = (float4*)&dst_s[(size_t)(n0 + lane + 32) * SDv + cb3];
                #pragma unroll
                for (int j4 = 0; j4 < 4; ++j4) {
                    float4 vv;
                    vv.x = sm[OX + (cb3 + 4*j4 + 0) * TEP + lane + 32] + m1[4*j4 + 0] + sm[OBn2 + cb3 + 4*j4 + 0];
                    vv.y = sm[OX + (cb3 + 4*j4 + 1) * TEP + lane + 32] + m1[4*j4 + 1] + sm[OBn2 + cb3 + 4*j4 + 1];
                    vv.z = sm[OX + (cb3 + 4*j4 + 2) * TEP + lane + 32] + m1[4*j4 + 2] + sm[OBn2 + cb3 + 4*j4 + 2];
                    vv.w = sm[OX + (cb3 + 4*j4 + 3) * TEP + lane + 32] + m1[4*j4 + 3] + sm[OBn2 + cb3 + 4*j4 + 3];
                    srow[j4] = vv;
                }
            }
        }

        // v update
        for (int idx = tid; idx < 9 * TILE; idx += NT) {
            int nl = idx / 9;
            if (nl >= nn) break;
            int c = idx - nl * 9;
            int n = n0 + nl;
            float nv = g_v[(size_t)n * 9 + c] + g_vagg[(size_t)n * 9 + c] * g_inv[n];
            if (last) out_v[(size_t)n * 9 + c] = nv;
            else      g_v[(size_t)n * 9 + c] = nv;
        }
        __syncthreads();
    }
}

// -------------------- launch --------------------
extern "C" void kernel_launch(void* const* d_in, const int* in_sizes, int n_in,
                              void* d_out, int out_size)
{
    const float* s   = (const float*)d_in[0];
    const float* v   = (const float*)d_in[1];
    const int*   ei  = (const int*)d_in[2];
    const float* dv  = (const float*)d_in[3];
    const float* rv  = (const float*)d_in[4];
    const float* W1  = (const float*)d_in[5];
    const float* b1  = (const float*)d_in[6];
    const float* W2  = (const float*)d_in[7];
    const float* b2  = (const float*)d_in[8];
    const float* W3  = (const float*)d_in[9];
    const float* b3  = (const float*)d_in[10];
    const float* Wn1 = (const float*)d_in[11];
    const float* bn1 = (const float*)d_in[12];
    const float* Wn2 = (const float*)d_in[13];
    const float* bn2 = (const float*)d_in[14];
    const int* dst = ei;
    const int* src = ei + Ee;
    float* outp = (float*)d_out;

    cudaFuncSetAttribute(k_edge, cudaFuncAttributeMaxDynamicSharedMemorySize, SME_BYTES);
    cudaFuncSetAttribute(k_pq,   cudaFuncAttributeMaxDynamicSharedMemorySize, SMP_BYTES);
    cudaFuncSetAttribute(k_node, cudaFuncAttributeMaxDynamicSharedMemorySize, SMN_BYTES);

    k_init<<<(Nn * SDv + 255) / 256, 256>>>(s, v);
    k_pq<<<888, NT, SMP_BYTES>>>(W1, 0);
    k_count<<<(Ee + 255) / 256, 256>>>(dst);
    k_edge<<<444, NT, SME_BYTES>>>(dst, src, dv, rv, W1, b1, W2, b2, W3, b3, 0);
    k_inv<<<(Nn + 255) / 256, 256>>>();
    k_node<<<148, NT, SMN_BYTES>>>(Wn1, bn1, Wn2, bn2, outp, 0, 0);

    for (int l = 1; l < 4; ++l) {
        k_pq<<<888, NT, SMP_BYTES>>>(W1, l);
        k_edge<<<444, NT, SME_BYTES>>>(dst, src, dv, rv, W1, b1, W2, b2, W3, b3, l);
        k_node<<<148, NT, SMN_BYTES>>>(Wn1, bn1, Wn2, bn2, outp, (l == 3) ? 1 : 0, l);
    }
}